// round 9
// baseline (speedup 1.0000x reference)
#include <cuda_runtime.h>
#include <math.h>

#define GRID_R 128
#define NCELL (GRID_R*GRID_R*GRID_R)
#define MAXQ 1100000

// 128^3 cells x 8 channels (7 used + 1 pad) = 64 MiB static scratch
__device__ float g_grid[NCELL * 8];
// per-query reduced gather result (8 floats: 7 channels + pad), 32B/query
__device__ float g_raw[MAXQ * 8];

__device__ __forceinline__ float gelu_f(float x) {
    float t = tanhf(0.7978845608028654f * (x + 0.044715f * x * x * x));
    return 0.5f * x * (1.0f + t);
}

// ---------------- packed f32x2 helpers (sm_103a FFMA2 path) ----------------
__device__ __forceinline__ unsigned long long pk2(float lo, float hi) {
    unsigned long long r;
    asm("mov.b64 %0, {%1, %2};" : "=l"(r) : "f"(lo), "f"(hi));
    return r;
}
__device__ __forceinline__ void upk2(unsigned long long v, float& lo, float& hi) {
    asm("mov.b64 {%0, %1}, %2;" : "=f"(lo), "=f"(hi) : "l"(v));
}
__device__ __forceinline__ unsigned long long ffma2(unsigned long long a,
                                                    unsigned long long b,
                                                    unsigned long long c) {
    unsigned long long d;
    asm("fma.rn.f32x2 %0, %1, %2, %3;" : "=l"(d) : "l"(a), "l"(b), "l"(c));
    return d;
}

// ---------------------------------------------------------------------------
// Kernel 1: zero the grid (grid-stride)
// ---------------------------------------------------------------------------
__global__ void zero_grid_kernel() {
    float4* g = reinterpret_cast<float4*>(g_grid);
    unsigned stride = gridDim.x * blockDim.x;
    for (unsigned i = blockIdx.x * blockDim.x + threadIdx.x;
         i < (unsigned)(NCELL * 2); i += stride) {
        g[i] = make_float4(0.f, 0.f, 0.f, 0.f);
    }
}

// ---------------------------------------------------------------------------
// Kernel 2: particle-to-grid trilinear scatter (vector reductions)
// ---------------------------------------------------------------------------
__device__ __forceinline__ void red_add_v4(float* addr, float a, float b, float c, float d) {
    asm volatile("red.global.add.v4.f32 [%0], {%1,%2,%3,%4};"
                 :: "l"(addr), "f"(a), "f"(b), "f"(c), "f"(d) : "memory");
}

__global__ __launch_bounds__(256) void p2g_kernel(
    const float* __restrict__ src_ref,
    const float* __restrict__ src_curr,
    const float* __restrict__ Wf,
    const float* __restrict__ bf,
    int N) {
    int i = blockIdx.x * blockDim.x + threadIdx.x;
    if (i >= N) return;

    float xs0 = fminf(fmaxf(src_ref[3 * i + 0], 0.f), 1.f);
    float xs1 = fminf(fmaxf(src_ref[3 * i + 1], 0.f), 1.f);
    float xs2 = fminf(fmaxf(src_ref[3 * i + 2], 0.f), 1.f);
    float u0 = src_curr[3 * i + 0] - xs0;
    float u1 = src_curr[3 * i + 1] - xs1;
    float u2 = src_curr[3 * i + 2] - xs2;

    float f0 = gelu_f(bf[0] + u0 * Wf[0] + u1 * Wf[3] + u2 * Wf[6]);
    float f1 = gelu_f(bf[1] + u0 * Wf[1] + u1 * Wf[4] + u2 * Wf[7]);
    float f2 = gelu_f(bf[2] + u0 * Wf[2] + u1 * Wf[5] + u2 * Wf[8]);

    float cx = fminf(xs0 * 127.f, 126.999f);
    float cy = fminf(xs1 * 127.f, 126.999f);
    float cz = fminf(xs2 * 127.f, 126.999f);
    int bx = (int)cx, by = (int)cy, bz = (int)cz;
    float dx = cx - (float)bx, dy = cy - (float)by, dz = cz - (float)bz;

#pragma unroll
    for (int ox = 0; ox < 2; ox++) {
        float wx = ox ? dx : 1.f - dx;
#pragma unroll
        for (int oy = 0; oy < 2; oy++) {
            float wxy = wx * (oy ? dy : 1.f - dy);
#pragma unroll
            for (int oz = 0; oz < 2; oz++) {
                float w = wxy * (oz ? dz : 1.f - dz);
                int cell = ((((bx + ox) << 7) + (by + oy)) << 7) + (bz + oz);
                float* p = g_grid + cell * 8;
                red_add_v4(p,     f0 * w, f1 * w, f2 * w, w);
                red_add_v4(p + 4, u0 * w, u1 * w, u2 * w, 0.f);
            }
        }
    }
}

// ---------------------------------------------------------------------------
// threefry2x32 with key = (0, 42), matching jax.random.key(42)
// ---------------------------------------------------------------------------
__device__ __forceinline__ void tf_round(unsigned& v0, unsigned& v1, int r) {
    v0 += v1;
    v1 = __funnelshift_l(v1, v1, r);
    v1 ^= v0;
}

__device__ __forceinline__ uint2 threefry_0_42(unsigned x0, unsigned x1) {
    const unsigned k0 = 0u, k1 = 42u;
    const unsigned k2 = 0u ^ 42u ^ 0x1BD11BDAu;
    unsigned v0 = x0 + k0, v1 = x1 + k1;
    tf_round(v0, v1, 13); tf_round(v0, v1, 15); tf_round(v0, v1, 26); tf_round(v0, v1, 6);
    v0 += k1; v1 += k2 + 1u;
    tf_round(v0, v1, 17); tf_round(v0, v1, 29); tf_round(v0, v1, 16); tf_round(v0, v1, 24);
    v0 += k2; v1 += k0 + 2u;
    tf_round(v0, v1, 13); tf_round(v0, v1, 15); tf_round(v0, v1, 26); tf_round(v0, v1, 6);
    v0 += k0; v1 += k1 + 3u;
    tf_round(v0, v1, 17); tf_round(v0, v1, 29); tf_round(v0, v1, 16); tf_round(v0, v1, 24);
    v0 += k1; v1 += k2 + 4u;
    tf_round(v0, v1, 13); tf_round(v0, v1, 15); tf_round(v0, v1, 26); tf_round(v0, v1, 6);
    v0 += k2; v1 += k0 + 5u;
    return make_uint2(v0, v1);
}

// jax_threefry_partitionable=True: bits[j] = w0 ^ w1 of threefry(key, (0, j))
__device__ __forceinline__ unsigned tf_bits_partitionable(unsigned j) {
    uint2 r = threefry_0_42(0u, j);
    return r.x ^ r.y;
}

__device__ __forceinline__ float bits_to_normal(unsigned b) {
    float f = __uint_as_float((b >> 9) | 0x3f800000u) - 1.0f;
    float u = f * 2.0f - 0.99999994f;
    u = fmaxf(u, -0.99999994f);
    return 1.4142135623730951f * erfinvf(u);
}

// ---------------------------------------------------------------------------
// Kernel 3: gather — 8 threads per query (one per MC path), shfl-reduce
// ---------------------------------------------------------------------------
__global__ __launch_bounds__(256) void gather_kernel(
    const float* __restrict__ xq_in, int M) {

    int tid = blockIdx.x * blockDim.x + threadIdx.x;
    int m  = tid >> 3;
    int kk = tid & 7;
    if (m >= M) return;

    float q0 = fminf(fmaxf(xq_in[3 * m + 0], 0.f), 1.f) * 127.f;
    float q1 = fminf(fmaxf(xq_in[3 * m + 1], 0.f), 1.f) * 127.f;
    float q2 = fminf(fmaxf(xq_in[3 * m + 2], 0.f), 1.f) * 127.f;

    unsigned jb = ((unsigned)kk * (unsigned)M + (unsigned)m) * 3u;
    float px = q0 + 0.8f * bits_to_normal(tf_bits_partitionable(jb + 0u));
    float py = q1 + 0.8f * bits_to_normal(tf_bits_partitionable(jb + 1u));
    float pz = q2 + 0.8f * bits_to_normal(tf_bits_partitionable(jb + 2u));

    float fx = floorf(px), fy = floorf(py), fz = floorf(pz);
    float dx = px - fx, dy = py - fy, dz = pz - fz;
    int lx = (int)fx, ly = (int)fy, lz = (int)fz;
    int x0i = min(max(lx, 0), 127), x1i = min(max(lx + 1, 0), 127);
    int y0i = min(max(ly, 0), 127), y1i = min(max(ly + 1, 0), 127);
    int z0i = min(max(lz, 0), 127), z1i = min(max(lz + 1, 0), 127);

    // packed accumulators: (ch0,ch1) (ch2,ch3) (ch4,ch5) (ch6,pad)
    unsigned long long acc01 = 0ull, acc23 = 0ull, acc45 = 0ull, acc67 = 0ull;

#pragma unroll
    for (int cx = 0; cx < 2; cx++) {
        int ix = cx ? x1i : x0i;
        float wx = cx ? dx : 1.f - dx;
#pragma unroll
        for (int cy = 0; cy < 2; cy++) {
            int iy = cy ? y1i : y0i;
            float wxy = wx * (cy ? dy : 1.f - dy);
#pragma unroll
            for (int cz = 0; cz < 2; cz++) {
                int iz = cz ? z1i : z0i;
                float w = wxy * (cz ? dz : 1.f - dz);
                int cell = (((ix << 7) + iy) << 7) + iz;
                const ulonglong2* g =
                    reinterpret_cast<const ulonglong2*>(g_grid + cell * 8);
                ulonglong2 va = g[0];
                ulonglong2 vb = g[1];
                unsigned long long ws = pk2(w, w);
                acc01 = ffma2(va.x, ws, acc01);
                acc23 = ffma2(va.y, ws, acc23);
                acc45 = ffma2(vb.x, ws, acc45);
                acc67 = ffma2(vb.y, ws, acc67);
            }
        }
    }

    // butterfly reduce over the 8 path-lanes (lanes differ only in kk bits)
#pragma unroll
    for (int d = 4; d >= 1; d >>= 1) {
        float lo, hi, slo, shi;
        upk2(acc01, lo, hi);
        slo = __shfl_xor_sync(0xffffffffu, lo, d);
        shi = __shfl_xor_sync(0xffffffffu, hi, d);
        acc01 = pk2(lo + slo, hi + shi);
        upk2(acc23, lo, hi);
        slo = __shfl_xor_sync(0xffffffffu, lo, d);
        shi = __shfl_xor_sync(0xffffffffu, hi, d);
        acc23 = pk2(lo + slo, hi + shi);
        upk2(acc45, lo, hi);
        slo = __shfl_xor_sync(0xffffffffu, lo, d);
        shi = __shfl_xor_sync(0xffffffffu, hi, d);
        acc45 = pk2(lo + slo, hi + shi);
        upk2(acc67, lo, hi);
        slo = __shfl_xor_sync(0xffffffffu, lo, d);
        shi = __shfl_xor_sync(0xffffffffu, hi, d);
        acc67 = pk2(lo + slo, hi + shi);
    }

    if (kk == 0) {
        ulonglong2* dst = reinterpret_cast<ulonglong2*>(g_raw + (size_t)m * 8);
        ulonglong2 v0; v0.x = acc01; v0.y = acc23;
        ulonglong2 v1; v1.x = acc45; v1.y = acc67;
        dst[0] = v0;
        dst[1] = v1;
    }
}

// ---------------------------------------------------------------------------
// Kernel 4: per-query MLP decode (FFMA2)
// ---------------------------------------------------------------------------
__global__ __launch_bounds__(256) void mlp_kernel(
    const float* __restrict__ xq_in,
    const float* __restrict__ W1, const float* __restrict__ b1,
    const float* __restrict__ W2, const float* __restrict__ b2,
    const float* __restrict__ W3, const float* __restrict__ b3,
    float* __restrict__ out, int M) {

    __shared__ float sW1t[24 * 64];   // [j][i], i contiguous
    __shared__ float sW2t[64 * 64];   // [j][i]
    __shared__ float sW3p[64 * 4];
    __shared__ float sb1[64], sb2[64], sb3[3];

    for (int t = threadIdx.x; t < 24 * 64; t += blockDim.x) {
        int j = t / 24, i = t % 24;
        sW1t[t] = W1[i * 64 + j];
    }
    for (int t = threadIdx.x; t < 64 * 64; t += blockDim.x) {
        int j = t >> 6, i = t & 63;
        sW2t[t] = W2[i * 64 + j];
    }
    for (int t = threadIdx.x; t < 192; t += blockDim.x) {
        int j = t / 3, c = t % 3;
        sW3p[j * 4 + c] = W3[t];
    }
    for (int t = threadIdx.x; t < 64; t += blockDim.x) {
        sb1[t] = b1[t];
        sb2[t] = b2[t];
    }
    if (threadIdx.x < 3) sb3[threadIdx.x] = b3[threadIdx.x];
    __syncthreads();

    int m = blockIdx.x * blockDim.x + threadIdx.x;
    if (m >= M) return;

    const float4* raw = reinterpret_cast<const float4*>(g_raw + (size_t)m * 8);
    float4 ra = raw[0];   // a0 a1 a2 a3
    float4 rb = raw[1];   // a4 a5 a6 pad

    float xq0 = fminf(fmaxf(xq_in[3 * m + 0], 0.f), 1.f);
    float xq1 = fminf(fmaxf(xq_in[3 * m + 1], 0.f), 1.f);
    float xq2 = fminf(fmaxf(xq_in[3 * m + 2], 0.f), 1.f);

    float r3 = ra.w * 0.125f;
    float denom = fmaxf(r3, 1e-5f);
    float s = (r3 > 1e-5f) ? (0.125f / denom) : 0.f;

    float dec[24];
    dec[0] = ra.x * s; dec[1] = ra.y * s; dec[2] = ra.z * s;
    float un0 = rb.x * s, un1 = rb.y * s, un2 = rb.z * s;
    dec[3] = un0; dec[4] = un1; dec[5] = un2;

    const float PI = 3.14159265358979323846f;
    {
        float s1, c1;
        __sincosf(PI * xq0, &s1, &c1);
        float s2 = 2.f * s1 * c1, c2 = 1.f - 2.f * s1 * s1;
        float s4 = 2.f * s2 * c2, c4 = 1.f - 2.f * s2 * s2;
        dec[6] = s1; dec[9] = c1; dec[12] = s2; dec[15] = c2; dec[18] = s4; dec[21] = c4;
        __sincosf(PI * xq1, &s1, &c1);
        s2 = 2.f * s1 * c1; c2 = 1.f - 2.f * s1 * s1;
        s4 = 2.f * s2 * c2; c4 = 1.f - 2.f * s2 * s2;
        dec[7] = s1; dec[10] = c1; dec[13] = s2; dec[16] = c2; dec[19] = s4; dec[22] = c4;
        __sincosf(PI * xq2, &s1, &c1);
        s2 = 2.f * s1 * c1; c2 = 1.f - 2.f * s1 * s1;
        s4 = 2.f * s2 * c2; c4 = 1.f - 2.f * s2 * s2;
        dec[8] = s1; dec[11] = c1; dec[14] = s2; dec[17] = c2; dec[20] = s4; dec[23] = c4;
    }

    unsigned long long decp[12];
#pragma unroll
    for (int i = 0; i < 12; i++) decp[i] = pk2(dec[2 * i], dec[2 * i + 1]);

    // Layer 1: 24 -> 64 via FFMA2
    unsigned long long h1p[32];
#pragma unroll
    for (int j2 = 0; j2 < 32; j2++) {
        float tj[2];
#pragma unroll
        for (int half = 0; half < 2; half++) {
            int j = j2 * 2 + half;
            const ulonglong2* w = reinterpret_cast<const ulonglong2*>(sW1t + j * 24);
            unsigned long long acc = pk2(sb1[j], 0.f);
#pragma unroll
            for (int i = 0; i < 6; i++) {
                ulonglong2 wv = w[i];
                acc = ffma2(decp[2 * i + 0], wv.x, acc);
                acc = ffma2(decp[2 * i + 1], wv.y, acc);
            }
            float lo, hi;
            upk2(acc, lo, hi);
            tj[half] = gelu_f(lo + hi);
        }
        h1p[j2] = pk2(tj[0], tj[1]);
    }

    // Layer 2 (64->64, FFMA2) fused with layer 3 (64->3)
    float r0 = sb3[0], r1 = sb3[1], r2 = sb3[2];
#pragma unroll 4
    for (int j = 0; j < 64; j++) {
        const ulonglong2* w = reinterpret_cast<const ulonglong2*>(sW2t + j * 64);
        unsigned long long acc = pk2(sb2[j], 0.f);
#pragma unroll
        for (int i = 0; i < 16; i++) {
            ulonglong2 wv = w[i];
            acc = ffma2(h1p[2 * i + 0], wv.x, acc);
            acc = ffma2(h1p[2 * i + 1], wv.y, acc);
        }
        float lo, hi;
        upk2(acc, lo, hi);
        float g = gelu_f(lo + hi);
        r0 += g * sW3p[j * 4 + 0];
        r1 += g * sW3p[j * 4 + 1];
        r2 += g * sW3p[j * 4 + 2];
    }

    out[3 * m + 0] = fminf(fmaxf(un0 + r0, 0.001f), 0.999f);
    out[3 * m + 1] = fminf(fmaxf(un1 + r1, 0.001f), 0.999f);
    out[3 * m + 2] = fminf(fmaxf(un2 + r2, 0.001f), 0.999f);
}

// ---------------------------------------------------------------------------
extern "C" void kernel_launch(void* const* d_in, const int* in_sizes, int n_in,
                              void* d_out, int out_size) {
    const float* xq  = (const float*)d_in[0];
    const float* xsr = (const float*)d_in[1];
    const float* xsc = (const float*)d_in[2];
    const float* Wf  = (const float*)d_in[3];
    const float* bf  = (const float*)d_in[4];
    const float* W1  = (const float*)d_in[5];
    const float* b1  = (const float*)d_in[6];
    const float* W2  = (const float*)d_in[7];
    const float* b2  = (const float*)d_in[8];
    const float* W3  = (const float*)d_in[9];
    const float* b3  = (const float*)d_in[10];
    int M = in_sizes[0] / 3;
    int N = in_sizes[1] / 3;

    zero_grid_kernel<<<2048, 256>>>();
    p2g_kernel<<<(N + 255) / 256, 256>>>(xsr, xsc, Wf, bf, N);
    long long nthreads = (long long)M * 8;
    gather_kernel<<<(unsigned)((nthreads + 255) / 256), 256>>>(xq, M);
    mlp_kernel<<<(M + 255) / 256, 256>>>(xq, W1, b1, W2, b2, W3, b3,
                                         (float*)d_out, M);
}

// round 10
// speedup vs baseline: 1.8137x; 1.8137x over previous
#include <cuda_runtime.h>
#include <math.h>

#define GRID_R 128
#define NCELL (GRID_R*GRID_R*GRID_R)
#define MAXQ 1100000
#define QB 128

// 128^3 cells x 8 channels (7 used + 1 pad) = 64 MiB static scratch
__device__ float g_grid[NCELL * 8];
// per-query reduced gather result (8 floats: 7 channels + pad), 32B/query
__device__ float g_raw[MAXQ * 8];

__device__ __forceinline__ float gelu_f(float x) {
    float t = tanhf(0.7978845608028654f * (x + 0.044715f * x * x * x));
    return 0.5f * x * (1.0f + t);
}

// ---------------- packed f32x2 helpers (sm_103a FFMA2 path) ----------------
__device__ __forceinline__ unsigned long long pk2(float lo, float hi) {
    unsigned long long r;
    asm("mov.b64 %0, {%1, %2};" : "=l"(r) : "f"(lo), "f"(hi));
    return r;
}
__device__ __forceinline__ void upk2(unsigned long long v, float& lo, float& hi) {
    asm("mov.b64 {%0, %1}, %2;" : "=f"(lo), "=f"(hi) : "l"(v));
}
__device__ __forceinline__ unsigned long long ffma2(unsigned long long a,
                                                    unsigned long long b,
                                                    unsigned long long c) {
    unsigned long long d;
    asm("fma.rn.f32x2 %0, %1, %2, %3;" : "=l"(d) : "l"(a), "l"(b), "l"(c));
    return d;
}

// ---------------------------------------------------------------------------
// Kernel 1: zero the grid (grid-stride)
// ---------------------------------------------------------------------------
__global__ void zero_grid_kernel() {
    float4* g = reinterpret_cast<float4*>(g_grid);
    unsigned stride = gridDim.x * blockDim.x;
    for (unsigned i = blockIdx.x * blockDim.x + threadIdx.x;
         i < (unsigned)(NCELL * 2); i += stride) {
        g[i] = make_float4(0.f, 0.f, 0.f, 0.f);
    }
}

// ---------------------------------------------------------------------------
// Kernel 2: particle-to-grid trilinear scatter (vector reductions)
// ---------------------------------------------------------------------------
__device__ __forceinline__ void red_add_v4(float* addr, float a, float b, float c, float d) {
    asm volatile("red.global.add.v4.f32 [%0], {%1,%2,%3,%4};"
                 :: "l"(addr), "f"(a), "f"(b), "f"(c), "f"(d) : "memory");
}

__global__ __launch_bounds__(256) void p2g_kernel(
    const float* __restrict__ src_ref,
    const float* __restrict__ src_curr,
    const float* __restrict__ Wf,
    const float* __restrict__ bf,
    int N) {
    int i = blockIdx.x * blockDim.x + threadIdx.x;
    if (i >= N) return;

    float xs0 = fminf(fmaxf(src_ref[3 * i + 0], 0.f), 1.f);
    float xs1 = fminf(fmaxf(src_ref[3 * i + 1], 0.f), 1.f);
    float xs2 = fminf(fmaxf(src_ref[3 * i + 2], 0.f), 1.f);
    float u0 = src_curr[3 * i + 0] - xs0;
    float u1 = src_curr[3 * i + 1] - xs1;
    float u2 = src_curr[3 * i + 2] - xs2;

    float f0 = gelu_f(bf[0] + u0 * Wf[0] + u1 * Wf[3] + u2 * Wf[6]);
    float f1 = gelu_f(bf[1] + u0 * Wf[1] + u1 * Wf[4] + u2 * Wf[7]);
    float f2 = gelu_f(bf[2] + u0 * Wf[2] + u1 * Wf[5] + u2 * Wf[8]);

    float cx = fminf(xs0 * 127.f, 126.999f);
    float cy = fminf(xs1 * 127.f, 126.999f);
    float cz = fminf(xs2 * 127.f, 126.999f);
    int bx = (int)cx, by = (int)cy, bz = (int)cz;
    float dx = cx - (float)bx, dy = cy - (float)by, dz = cz - (float)bz;

#pragma unroll
    for (int ox = 0; ox < 2; ox++) {
        float wx = ox ? dx : 1.f - dx;
#pragma unroll
        for (int oy = 0; oy < 2; oy++) {
            float wxy = wx * (oy ? dy : 1.f - dy);
#pragma unroll
            for (int oz = 0; oz < 2; oz++) {
                float w = wxy * (oz ? dz : 1.f - dz);
                int cell = ((((bx + ox) << 7) + (by + oy)) << 7) + (bz + oz);
                float* p = g_grid + cell * 8;
                red_add_v4(p,     f0 * w, f1 * w, f2 * w, w);
                red_add_v4(p + 4, u0 * w, u1 * w, u2 * w, 0.f);
            }
        }
    }
}

// ---------------------------------------------------------------------------
// threefry2x32 with key = (0, 42), matching jax.random.key(42)
// ---------------------------------------------------------------------------
__device__ __forceinline__ void tf_round(unsigned& v0, unsigned& v1, int r) {
    v0 += v1;
    v1 = __funnelshift_l(v1, v1, r);
    v1 ^= v0;
}

__device__ __forceinline__ uint2 threefry_0_42(unsigned x0, unsigned x1) {
    const unsigned k0 = 0u, k1 = 42u;
    const unsigned k2 = 0u ^ 42u ^ 0x1BD11BDAu;
    unsigned v0 = x0 + k0, v1 = x1 + k1;
    tf_round(v0, v1, 13); tf_round(v0, v1, 15); tf_round(v0, v1, 26); tf_round(v0, v1, 6);
    v0 += k1; v1 += k2 + 1u;
    tf_round(v0, v1, 17); tf_round(v0, v1, 29); tf_round(v0, v1, 16); tf_round(v0, v1, 24);
    v0 += k2; v1 += k0 + 2u;
    tf_round(v0, v1, 13); tf_round(v0, v1, 15); tf_round(v0, v1, 26); tf_round(v0, v1, 6);
    v0 += k0; v1 += k1 + 3u;
    tf_round(v0, v1, 17); tf_round(v0, v1, 29); tf_round(v0, v1, 16); tf_round(v0, v1, 24);
    v0 += k1; v1 += k2 + 4u;
    tf_round(v0, v1, 13); tf_round(v0, v1, 15); tf_round(v0, v1, 26); tf_round(v0, v1, 6);
    v0 += k2; v1 += k0 + 5u;
    return make_uint2(v0, v1);
}

// jax_threefry_partitionable=True: bits[j] = w0 ^ w1 of threefry(key, (0, j))
__device__ __forceinline__ unsigned tf_bits_partitionable(unsigned j) {
    uint2 r = threefry_0_42(0u, j);
    return r.x ^ r.y;
}

__device__ __forceinline__ float bits_to_normal(unsigned b) {
    float f = __uint_as_float((b >> 9) | 0x3f800000u) - 1.0f;
    float u = f * 2.0f - 0.99999994f;
    u = fmaxf(u, -0.99999994f);
    return 1.4142135623730951f * erfinvf(u);
}

// ---------------------------------------------------------------------------
// Kernel 3: gather — 8 threads per query (one per MC path), shfl-reduce
// ---------------------------------------------------------------------------
__global__ __launch_bounds__(256) void gather_kernel(
    const float* __restrict__ xq_in, int M) {

    int tid = blockIdx.x * blockDim.x + threadIdx.x;
    int m  = tid >> 3;
    int kk = tid & 7;
    if (m >= M) return;

    float q0 = fminf(fmaxf(xq_in[3 * m + 0], 0.f), 1.f) * 127.f;
    float q1 = fminf(fmaxf(xq_in[3 * m + 1], 0.f), 1.f) * 127.f;
    float q2 = fminf(fmaxf(xq_in[3 * m + 2], 0.f), 1.f) * 127.f;

    unsigned jb = ((unsigned)kk * (unsigned)M + (unsigned)m) * 3u;
    float px = q0 + 0.8f * bits_to_normal(tf_bits_partitionable(jb + 0u));
    float py = q1 + 0.8f * bits_to_normal(tf_bits_partitionable(jb + 1u));
    float pz = q2 + 0.8f * bits_to_normal(tf_bits_partitionable(jb + 2u));

    float fx = floorf(px), fy = floorf(py), fz = floorf(pz);
    float dx = px - fx, dy = py - fy, dz = pz - fz;
    int lx = (int)fx, ly = (int)fy, lz = (int)fz;
    int x0i = min(max(lx, 0), 127), x1i = min(max(lx + 1, 0), 127);
    int y0i = min(max(ly, 0), 127), y1i = min(max(ly + 1, 0), 127);
    int z0i = min(max(lz, 0), 127), z1i = min(max(lz + 1, 0), 127);

    unsigned long long acc01 = 0ull, acc23 = 0ull, acc45 = 0ull, acc67 = 0ull;

#pragma unroll
    for (int cx = 0; cx < 2; cx++) {
        int ix = cx ? x1i : x0i;
        float wx = cx ? dx : 1.f - dx;
#pragma unroll
        for (int cy = 0; cy < 2; cy++) {
            int iy = cy ? y1i : y0i;
            float wxy = wx * (cy ? dy : 1.f - dy);
#pragma unroll
            for (int cz = 0; cz < 2; cz++) {
                int iz = cz ? z1i : z0i;
                float w = wxy * (cz ? dz : 1.f - dz);
                int cell = (((ix << 7) + iy) << 7) + iz;
                const ulonglong2* g =
                    reinterpret_cast<const ulonglong2*>(g_grid + cell * 8);
                ulonglong2 va = g[0];
                ulonglong2 vb = g[1];
                unsigned long long ws = pk2(w, w);
                acc01 = ffma2(va.x, ws, acc01);
                acc23 = ffma2(va.y, ws, acc23);
                acc45 = ffma2(vb.x, ws, acc45);
                acc67 = ffma2(vb.y, ws, acc67);
            }
        }
    }

#pragma unroll
    for (int d = 4; d >= 1; d >>= 1) {
        float lo, hi, slo, shi;
        upk2(acc01, lo, hi);
        slo = __shfl_xor_sync(0xffffffffu, lo, d);
        shi = __shfl_xor_sync(0xffffffffu, hi, d);
        acc01 = pk2(lo + slo, hi + shi);
        upk2(acc23, lo, hi);
        slo = __shfl_xor_sync(0xffffffffu, lo, d);
        shi = __shfl_xor_sync(0xffffffffu, hi, d);
        acc23 = pk2(lo + slo, hi + shi);
        upk2(acc45, lo, hi);
        slo = __shfl_xor_sync(0xffffffffu, lo, d);
        shi = __shfl_xor_sync(0xffffffffu, hi, d);
        acc45 = pk2(lo + slo, hi + shi);
        upk2(acc67, lo, hi);
        slo = __shfl_xor_sync(0xffffffffu, lo, d);
        shi = __shfl_xor_sync(0xffffffffu, hi, d);
        acc67 = pk2(lo + slo, hi + shi);
    }

    if (kk == 0) {
        ulonglong2* dst = reinterpret_cast<ulonglong2*>(g_raw + (size_t)m * 8);
        ulonglong2 v0; v0.x = acc01; v0.y = acc23;
        ulonglong2 v1; v1.x = acc45; v1.y = acc67;
        dst[0] = v0;
        dst[1] = v1;
    }
}

// ---------------------------------------------------------------------------
// Kernel 4: block-GEMM MLP — 128 queries/block, 8q x 8n register tiles
// ---------------------------------------------------------------------------
// dynamic smem layout (float indices)
#define OFF_W1 0        // 24*64   = 1536
#define OFF_W2 1536     // 64*64   = 4096
#define OFF_W3 5632     // 64*4    = 256
#define OFF_B1 5888     // 64
#define OFF_B2 5952     // 64
#define OFF_B3 6016     // 16 (pad)
#define OFF_A0 6032     // 24*128  = 3072  (also reused as phase-3 partials 8*128*3)
#define OFF_A1 9104     // 64*128  = 8192
#define SMEM_FLOATS 17296
#define SMEM_BYTES (SMEM_FLOATS * 4)

__global__ __launch_bounds__(QB) void mlp_kernel(
    const float* __restrict__ xq_in,
    const float* __restrict__ W1, const float* __restrict__ b1,
    const float* __restrict__ W2, const float* __restrict__ b2,
    const float* __restrict__ W3, const float* __restrict__ b3,
    float* __restrict__ out, int M) {

    extern __shared__ float sm[];
    int tid = threadIdx.x;

    // stage weights (all row-major [k][j] — direct copies)
    for (int t = tid; t < 1536; t += QB) sm[OFF_W1 + t] = W1[t];
    for (int t = tid; t < 4096; t += QB) sm[OFF_W2 + t] = W2[t];
    for (int t = tid; t < 192; t += QB) { int j = t / 3, c = t % 3; sm[OFF_W3 + j * 4 + c] = W3[t]; }
    for (int t = tid; t < 64; t += QB) { sm[OFF_B1 + t] = b1[t]; sm[OFF_B2 + t] = b2[t]; }
    if (tid < 3) sm[OFF_B3 + tid] = b3[tid];

    // ---- phase 0: per-thread dec[24] for query gq, store transposed A0[i][q]
    int gq = blockIdx.x * QB + tid;
    float un0 = 0.f, un1 = 0.f, un2 = 0.f;
    float dec[24];
#pragma unroll
    for (int i = 0; i < 24; i++) dec[i] = 0.f;

    if (gq < M) {
        const float4* raw = reinterpret_cast<const float4*>(g_raw + (size_t)gq * 8);
        float4 ra = raw[0];
        float4 rb = raw[1];
        float xq0 = fminf(fmaxf(xq_in[3 * gq + 0], 0.f), 1.f);
        float xq1 = fminf(fmaxf(xq_in[3 * gq + 1], 0.f), 1.f);
        float xq2 = fminf(fmaxf(xq_in[3 * gq + 2], 0.f), 1.f);

        float r3 = ra.w * 0.125f;
        float denom = fmaxf(r3, 1e-5f);
        float s = (r3 > 1e-5f) ? (0.125f / denom) : 0.f;

        dec[0] = ra.x * s; dec[1] = ra.y * s; dec[2] = ra.z * s;
        un0 = rb.x * s; un1 = rb.y * s; un2 = rb.z * s;
        dec[3] = un0; dec[4] = un1; dec[5] = un2;

        const float PI = 3.14159265358979323846f;
        float s1, c1;
        __sincosf(PI * xq0, &s1, &c1);
        float s2 = 2.f * s1 * c1, c2 = 1.f - 2.f * s1 * s1;
        float s4 = 2.f * s2 * c2, c4 = 1.f - 2.f * s2 * s2;
        dec[6] = s1; dec[9] = c1; dec[12] = s2; dec[15] = c2; dec[18] = s4; dec[21] = c4;
        __sincosf(PI * xq1, &s1, &c1);
        s2 = 2.f * s1 * c1; c2 = 1.f - 2.f * s1 * s1;
        s4 = 2.f * s2 * c2; c4 = 1.f - 2.f * s2 * s2;
        dec[7] = s1; dec[10] = c1; dec[13] = s2; dec[16] = c2; dec[19] = s4; dec[22] = c4;
        __sincosf(PI * xq2, &s1, &c1);
        s2 = 2.f * s1 * c1; c2 = 1.f - 2.f * s1 * s1;
        s4 = 2.f * s2 * c2; c4 = 1.f - 2.f * s2 * s2;
        dec[8] = s1; dec[11] = c1; dec[14] = s2; dec[17] = c2; dec[20] = s4; dec[23] = c4;
    }
#pragma unroll
    for (int i = 0; i < 24; i++) sm[OFF_A0 + i * 128 + tid] = dec[i];
    __syncthreads();

    int tq = tid & 15;   // query-tile index (8 queries each)
    int tj = tid >> 4;   // neuron-tile index (8 neurons each)

    // ---- phase 1: C1[q][j] = A0 @ W1 + b1 ; acc lanes = query pairs
    unsigned long long acc[4][8];
#pragma unroll
    for (int jj = 0; jj < 8; jj++) {
        float b = sm[OFF_B1 + tj * 8 + jj];
        unsigned long long bd = pk2(b, b);
#pragma unroll
        for (int qp = 0; qp < 4; qp++) acc[qp][jj] = bd;
    }
#pragma unroll 8
    for (int k = 0; k < 24; k++) {
        const ulonglong2* ap = reinterpret_cast<const ulonglong2*>(&sm[OFF_A0 + k * 128 + tq * 8]);
        ulonglong2 aA = ap[0], aB = ap[1];
        unsigned long long av[4] = {aA.x, aA.y, aB.x, aB.y};
        const float4* wp = reinterpret_cast<const float4*>(&sm[OFF_W1 + k * 64 + tj * 8]);
        float4 w0 = wp[0], w1 = wp[1];
        float wv[8] = {w0.x, w0.y, w0.z, w0.w, w1.x, w1.y, w1.z, w1.w};
#pragma unroll
        for (int jj = 0; jj < 8; jj++) {
            unsigned long long wd = pk2(wv[jj], wv[jj]);
#pragma unroll
            for (int qp = 0; qp < 4; qp++) acc[qp][jj] = ffma2(av[qp], wd, acc[qp][jj]);
        }
    }
    // gelu + store A1[j][q] (q-pair packed)
#pragma unroll
    for (int jj = 0; jj < 8; jj++) {
#pragma unroll
        for (int qp = 0; qp < 4; qp++) {
            float lo, hi;
            upk2(acc[jj % 1 == 0 ? qp : qp][jj], lo, hi);
            unsigned long long g = pk2(gelu_f(lo), gelu_f(hi));
            *reinterpret_cast<unsigned long long*>(
                &sm[OFF_A1 + (tj * 8 + jj) * 128 + tq * 8 + qp * 2]) = g;
        }
    }
    __syncthreads();

    // ---- phase 2: C2[q][j] = gelu(C1) @ W2 + b2
#pragma unroll
    for (int jj = 0; jj < 8; jj++) {
        float b = sm[OFF_B2 + tj * 8 + jj];
        unsigned long long bd = pk2(b, b);
#pragma unroll
        for (int qp = 0; qp < 4; qp++) acc[qp][jj] = bd;
    }
#pragma unroll 8
    for (int k = 0; k < 64; k++) {
        const ulonglong2* ap = reinterpret_cast<const ulonglong2*>(&sm[OFF_A1 + k * 128 + tq * 8]);
        ulonglong2 aA = ap[0], aB = ap[1];
        unsigned long long av[4] = {aA.x, aA.y, aB.x, aB.y};
        const float4* wp = reinterpret_cast<const float4*>(&sm[OFF_W2 + k * 64 + tj * 8]);
        float4 w0 = wp[0], w1 = wp[1];
        float wv[8] = {w0.x, w0.y, w0.z, w0.w, w1.x, w1.y, w1.z, w1.w};
#pragma unroll
        for (int jj = 0; jj < 8; jj++) {
            unsigned long long wd = pk2(wv[jj], wv[jj]);
#pragma unroll
            for (int qp = 0; qp < 4; qp++) acc[qp][jj] = ffma2(av[qp], wd, acc[qp][jj]);
        }
    }

    // ---- phase 3: r[q][c] = gelu(C2) @ W3 ; partials over this thread's 8 j's
    float r[8][3];
#pragma unroll
    for (int qq = 0; qq < 8; qq++) { r[qq][0] = 0.f; r[qq][1] = 0.f; r[qq][2] = 0.f; }
#pragma unroll
    for (int jj = 0; jj < 8; jj++) {
        int j = tj * 8 + jj;
        float w30 = sm[OFF_W3 + j * 4 + 0];
        float w31 = sm[OFF_W3 + j * 4 + 1];
        float w32 = sm[OFF_W3 + j * 4 + 2];
#pragma unroll
        for (int qp = 0; qp < 4; qp++) {
            float lo, hi;
            upk2(acc[qp][jj], lo, hi);
            float g0 = gelu_f(lo), g1 = gelu_f(hi);
            r[qp * 2 + 0][0] += g0 * w30; r[qp * 2 + 0][1] += g0 * w31; r[qp * 2 + 0][2] += g0 * w32;
            r[qp * 2 + 1][0] += g1 * w30; r[qp * 2 + 1][1] += g1 * w31; r[qp * 2 + 1][2] += g1 * w32;
        }
    }
    // write partials to A0 region (free after phase 1): [tj][q][c]
#pragma unroll
    for (int qq = 0; qq < 8; qq++) {
        int q = tq * 8 + qq;
        sm[OFF_A0 + tj * 384 + q * 3 + 0] = r[qq][0];
        sm[OFF_A0 + tj * 384 + q * 3 + 1] = r[qq][1];
        sm[OFF_A0 + tj * 384 + q * 3 + 2] = r[qq][2];
    }
    __syncthreads();

    // reduce 8 partials per query; thread tid owns query tid
    if (gq < M) {
        float r0 = sm[OFF_B3 + 0], r1 = sm[OFF_B3 + 1], r2 = sm[OFF_B3 + 2];
#pragma unroll
        for (int t = 0; t < 8; t++) {
            r0 += sm[OFF_A0 + t * 384 + tid * 3 + 0];
            r1 += sm[OFF_A0 + t * 384 + tid * 3 + 1];
            r2 += sm[OFF_A0 + t * 384 + tid * 3 + 2];
        }
        out[3 * gq + 0] = fminf(fmaxf(un0 + r0, 0.001f), 0.999f);
        out[3 * gq + 1] = fminf(fmaxf(un1 + r1, 0.001f), 0.999f);
        out[3 * gq + 2] = fminf(fmaxf(un2 + r2, 0.001f), 0.999f);
    }
}

// ---------------------------------------------------------------------------
extern "C" void kernel_launch(void* const* d_in, const int* in_sizes, int n_in,
                              void* d_out, int out_size) {
    const float* xq  = (const float*)d_in[0];
    const float* xsr = (const float*)d_in[1];
    const float* xsc = (const float*)d_in[2];
    const float* Wf  = (const float*)d_in[3];
    const float* bf  = (const float*)d_in[4];
    const float* W1  = (const float*)d_in[5];
    const float* b1  = (const float*)d_in[6];
    const float* W2  = (const float*)d_in[7];
    const float* b2  = (const float*)d_in[8];
    const float* W3  = (const float*)d_in[9];
    const float* b3  = (const float*)d_in[10];
    int M = in_sizes[0] / 3;
    int N = in_sizes[1] / 3;

    static int smem_set = 0;
    if (!smem_set) {
        cudaFuncSetAttribute(mlp_kernel,
                             cudaFuncAttributeMaxDynamicSharedMemorySize, SMEM_BYTES);
        smem_set = 1;
    }

    zero_grid_kernel<<<2048, 256>>>();
    p2g_kernel<<<(N + 255) / 256, 256>>>(xsr, xsc, Wf, bf, N);
    long long nthreads = (long long)M * 8;
    gather_kernel<<<(unsigned)((nthreads + 255) / 256), 256>>>(xq, M);
    mlp_kernel<<<(M + QB - 1) / QB, QB, SMEM_BYTES>>>(xq, W1, b1, W2, b2, W3, b3,
                                                      (float*)d_out, M);
}

// round 11
// speedup vs baseline: 1.8218x; 1.0045x over previous
#include <cuda_runtime.h>
#include <math.h>

#define GRID_R 128
#define NCELL (GRID_R*GRID_R*GRID_R)
#define MAXQ 1100000
#define QB 128

// 128^3 cells x 8 channels (7 used + 1 pad) = 64 MiB static scratch
__device__ float g_grid[NCELL * 8];
// per-query reduced gather result (8 floats: 7 channels + pad), 32B/query
__device__ float g_raw[MAXQ * 8];

// fast gelu: tanh via overflow-safe exp identity (MUFU EX2 + MUFU div)
// tanh(y) = sign(y) * (1 - e) / (1 + e), e = exp(-2|y|)
__device__ __forceinline__ float gelu_f(float x) {
    const float C  = 0.7978845608028654f;
    const float C3 = 0.7978845608028654f * 0.044715f;
    float y = x * (C + C3 * x * x);
    float a = fabsf(y);
    float e = __expf(-2.f * a);
    float t = __fdividef(1.f - e, 1.f + e);
    t = copysignf(t, y);
    return 0.5f * x * (1.f + t);
}

// ---------------- packed f32x2 helpers (sm_103a FFMA2 path) ----------------
__device__ __forceinline__ unsigned long long pk2(float lo, float hi) {
    unsigned long long r;
    asm("mov.b64 %0, {%1, %2};" : "=l"(r) : "f"(lo), "f"(hi));
    return r;
}
__device__ __forceinline__ void upk2(unsigned long long v, float& lo, float& hi) {
    asm("mov.b64 {%0, %1}, %2;" : "=f"(lo), "=f"(hi) : "l"(v));
}
__device__ __forceinline__ unsigned long long ffma2(unsigned long long a,
                                                    unsigned long long b,
                                                    unsigned long long c) {
    unsigned long long d;
    asm("fma.rn.f32x2 %0, %1, %2, %3;" : "=l"(d) : "l"(a), "l"(b), "l"(c));
    return d;
}

// ---------------------------------------------------------------------------
// Kernel 1: zero the grid (grid-stride)
// ---------------------------------------------------------------------------
__global__ void zero_grid_kernel() {
    float4* g = reinterpret_cast<float4*>(g_grid);
    unsigned stride = gridDim.x * blockDim.x;
    for (unsigned i = blockIdx.x * blockDim.x + threadIdx.x;
         i < (unsigned)(NCELL * 2); i += stride) {
        g[i] = make_float4(0.f, 0.f, 0.f, 0.f);
    }
}

// ---------------------------------------------------------------------------
// Kernel 2: particle-to-grid trilinear scatter (vector reductions)
// ---------------------------------------------------------------------------
__device__ __forceinline__ void red_add_v4(float* addr, float a, float b, float c, float d) {
    asm volatile("red.global.add.v4.f32 [%0], {%1,%2,%3,%4};"
                 :: "l"(addr), "f"(a), "f"(b), "f"(c), "f"(d) : "memory");
}

__global__ __launch_bounds__(256) void p2g_kernel(
    const float* __restrict__ src_ref,
    const float* __restrict__ src_curr,
    const float* __restrict__ Wf,
    const float* __restrict__ bf,
    int N) {
    int i = blockIdx.x * blockDim.x + threadIdx.x;
    if (i >= N) return;

    float xs0 = fminf(fmaxf(src_ref[3 * i + 0], 0.f), 1.f);
    float xs1 = fminf(fmaxf(src_ref[3 * i + 1], 0.f), 1.f);
    float xs2 = fminf(fmaxf(src_ref[3 * i + 2], 0.f), 1.f);
    float u0 = src_curr[3 * i + 0] - xs0;
    float u1 = src_curr[3 * i + 1] - xs1;
    float u2 = src_curr[3 * i + 2] - xs2;

    float f0 = gelu_f(bf[0] + u0 * Wf[0] + u1 * Wf[3] + u2 * Wf[6]);
    float f1 = gelu_f(bf[1] + u0 * Wf[1] + u1 * Wf[4] + u2 * Wf[7]);
    float f2 = gelu_f(bf[2] + u0 * Wf[2] + u1 * Wf[5] + u2 * Wf[8]);

    float cx = fminf(xs0 * 127.f, 126.999f);
    float cy = fminf(xs1 * 127.f, 126.999f);
    float cz = fminf(xs2 * 127.f, 126.999f);
    int bx = (int)cx, by = (int)cy, bz = (int)cz;
    float dx = cx - (float)bx, dy = cy - (float)by, dz = cz - (float)bz;

#pragma unroll
    for (int ox = 0; ox < 2; ox++) {
        float wx = ox ? dx : 1.f - dx;
#pragma unroll
        for (int oy = 0; oy < 2; oy++) {
            float wxy = wx * (oy ? dy : 1.f - dy);
#pragma unroll
            for (int oz = 0; oz < 2; oz++) {
                float w = wxy * (oz ? dz : 1.f - dz);
                int cell = ((((bx + ox) << 7) + (by + oy)) << 7) + (bz + oz);
                float* p = g_grid + cell * 8;
                red_add_v4(p,     f0 * w, f1 * w, f2 * w, w);
                red_add_v4(p + 4, u0 * w, u1 * w, u2 * w, 0.f);
            }
        }
    }
}

// ---------------------------------------------------------------------------
// threefry2x32 with key = (0, 42), matching jax.random.key(42)
// ---------------------------------------------------------------------------
__device__ __forceinline__ void tf_round(unsigned& v0, unsigned& v1, int r) {
    v0 += v1;
    v1 = __funnelshift_l(v1, v1, r);
    v1 ^= v0;
}

__device__ __forceinline__ uint2 threefry_0_42(unsigned x0, unsigned x1) {
    const unsigned k0 = 0u, k1 = 42u;
    const unsigned k2 = 0u ^ 42u ^ 0x1BD11BDAu;
    unsigned v0 = x0 + k0, v1 = x1 + k1;
    tf_round(v0, v1, 13); tf_round(v0, v1, 15); tf_round(v0, v1, 26); tf_round(v0, v1, 6);
    v0 += k1; v1 += k2 + 1u;
    tf_round(v0, v1, 17); tf_round(v0, v1, 29); tf_round(v0, v1, 16); tf_round(v0, v1, 24);
    v0 += k2; v1 += k0 + 2u;
    tf_round(v0, v1, 13); tf_round(v0, v1, 15); tf_round(v0, v1, 26); tf_round(v0, v1, 6);
    v0 += k0; v1 += k1 + 3u;
    tf_round(v0, v1, 17); tf_round(v0, v1, 29); tf_round(v0, v1, 16); tf_round(v0, v1, 24);
    v0 += k1; v1 += k2 + 4u;
    tf_round(v0, v1, 13); tf_round(v0, v1, 15); tf_round(v0, v1, 26); tf_round(v0, v1, 6);
    v0 += k2; v1 += k0 + 5u;
    return make_uint2(v0, v1);
}

// jax_threefry_partitionable=True: bits[j] = w0 ^ w1 of threefry(key, (0, j))
__device__ __forceinline__ unsigned tf_bits_partitionable(unsigned j) {
    uint2 r = threefry_0_42(0u, j);
    return r.x ^ r.y;
}

__device__ __forceinline__ float bits_to_normal(unsigned b) {
    float f = __uint_as_float((b >> 9) | 0x3f800000u) - 1.0f;
    float u = f * 2.0f - 0.99999994f;
    u = fmaxf(u, -0.99999994f);
    return 1.4142135623730951f * erfinvf(u);
}

// ---------------------------------------------------------------------------
// Kernel 3: gather — 8 threads per query (one per MC path), shfl-reduce
// ---------------------------------------------------------------------------
__global__ __launch_bounds__(256) void gather_kernel(
    const float* __restrict__ xq_in, int M) {

    int tid = blockIdx.x * blockDim.x + threadIdx.x;
    int m  = tid >> 3;
    int kk = tid & 7;
    if (m >= M) return;

    float q0 = fminf(fmaxf(xq_in[3 * m + 0], 0.f), 1.f) * 127.f;
    float q1 = fminf(fmaxf(xq_in[3 * m + 1], 0.f), 1.f) * 127.f;
    float q2 = fminf(fmaxf(xq_in[3 * m + 2], 0.f), 1.f) * 127.f;

    unsigned jb = ((unsigned)kk * (unsigned)M + (unsigned)m) * 3u;
    float px = q0 + 0.8f * bits_to_normal(tf_bits_partitionable(jb + 0u));
    float py = q1 + 0.8f * bits_to_normal(tf_bits_partitionable(jb + 1u));
    float pz = q2 + 0.8f * bits_to_normal(tf_bits_partitionable(jb + 2u));

    float fx = floorf(px), fy = floorf(py), fz = floorf(pz);
    float dx = px - fx, dy = py - fy, dz = pz - fz;
    int lx = (int)fx, ly = (int)fy, lz = (int)fz;
    int x0i = min(max(lx, 0), 127), x1i = min(max(lx + 1, 0), 127);
    int y0i = min(max(ly, 0), 127), y1i = min(max(ly + 1, 0), 127);
    int z0i = min(max(lz, 0), 127), z1i = min(max(lz + 1, 0), 127);

    unsigned long long acc01 = 0ull, acc23 = 0ull, acc45 = 0ull, acc67 = 0ull;

#pragma unroll
    for (int cx = 0; cx < 2; cx++) {
        int ix = cx ? x1i : x0i;
        float wx = cx ? dx : 1.f - dx;
#pragma unroll
        for (int cy = 0; cy < 2; cy++) {
            int iy = cy ? y1i : y0i;
            float wxy = wx * (cy ? dy : 1.f - dy);
#pragma unroll
            for (int cz = 0; cz < 2; cz++) {
                int iz = cz ? z1i : z0i;
                float w = wxy * (cz ? dz : 1.f - dz);
                int cell = (((ix << 7) + iy) << 7) + iz;
                const ulonglong2* g =
                    reinterpret_cast<const ulonglong2*>(g_grid + cell * 8);
                ulonglong2 va = g[0];
                ulonglong2 vb = g[1];
                unsigned long long ws = pk2(w, w);
                acc01 = ffma2(va.x, ws, acc01);
                acc23 = ffma2(va.y, ws, acc23);
                acc45 = ffma2(vb.x, ws, acc45);
                acc67 = ffma2(vb.y, ws, acc67);
            }
        }
    }

#pragma unroll
    for (int d = 4; d >= 1; d >>= 1) {
        float lo, hi, slo, shi;
        upk2(acc01, lo, hi);
        slo = __shfl_xor_sync(0xffffffffu, lo, d);
        shi = __shfl_xor_sync(0xffffffffu, hi, d);
        acc01 = pk2(lo + slo, hi + shi);
        upk2(acc23, lo, hi);
        slo = __shfl_xor_sync(0xffffffffu, lo, d);
        shi = __shfl_xor_sync(0xffffffffu, hi, d);
        acc23 = pk2(lo + slo, hi + shi);
        upk2(acc45, lo, hi);
        slo = __shfl_xor_sync(0xffffffffu, lo, d);
        shi = __shfl_xor_sync(0xffffffffu, hi, d);
        acc45 = pk2(lo + slo, hi + shi);
        upk2(acc67, lo, hi);
        slo = __shfl_xor_sync(0xffffffffu, lo, d);
        shi = __shfl_xor_sync(0xffffffffu, hi, d);
        acc67 = pk2(lo + slo, hi + shi);
    }

    if (kk == 0) {
        ulonglong2* dst = reinterpret_cast<ulonglong2*>(g_raw + (size_t)m * 8);
        ulonglong2 v0; v0.x = acc01; v0.y = acc23;
        ulonglong2 v1; v1.x = acc45; v1.y = acc67;
        dst[0] = v0;
        dst[1] = v1;
    }
}

// ---------------------------------------------------------------------------
// Kernel 4: block-GEMM MLP — 128 queries/block, 8q x 8n register tiles
// ---------------------------------------------------------------------------
// dynamic smem layout (float indices)
#define OFF_W1 0        // 24*64   = 1536
#define OFF_W2 1536     // 64*64   = 4096
#define OFF_W3 5632     // 64*4    = 256
#define OFF_B1 5888     // 64
#define OFF_B2 5952     // 64
#define OFF_B3 6016     // 16 (pad)
#define OFF_A0 6032     // 24*128  = 3072  (also reused as phase-3 partials 8*128*3)
#define OFF_A1 9104     // 64*128  = 8192
#define SMEM_FLOATS 17296
#define SMEM_BYTES (SMEM_FLOATS * 4)

__global__ __launch_bounds__(QB) void mlp_kernel(
    const float* __restrict__ xq_in,
    const float* __restrict__ W1, const float* __restrict__ b1,
    const float* __restrict__ W2, const float* __restrict__ b2,
    const float* __restrict__ W3, const float* __restrict__ b3,
    float* __restrict__ out, int M) {

    extern __shared__ float sm[];
    int tid = threadIdx.x;

    // stage weights (all row-major [k][j] — direct copies)
    for (int t = tid; t < 1536; t += QB) sm[OFF_W1 + t] = W1[t];
    for (int t = tid; t < 4096; t += QB) sm[OFF_W2 + t] = W2[t];
    for (int t = tid; t < 192; t += QB) { int j = t / 3, c = t % 3; sm[OFF_W3 + j * 4 + c] = W3[t]; }
    for (int t = tid; t < 64; t += QB) { sm[OFF_B1 + t] = b1[t]; sm[OFF_B2 + t] = b2[t]; }
    if (tid < 3) sm[OFF_B3 + tid] = b3[tid];

    // ---- phase 0: per-thread dec[24] for query gq, store transposed A0[i][q]
    int gq = blockIdx.x * QB + tid;
    float un0 = 0.f, un1 = 0.f, un2 = 0.f;
    float dec[24];
#pragma unroll
    for (int i = 0; i < 24; i++) dec[i] = 0.f;

    if (gq < M) {
        const float4* raw = reinterpret_cast<const float4*>(g_raw + (size_t)gq * 8);
        float4 ra = raw[0];
        float4 rb = raw[1];
        float xq0 = fminf(fmaxf(xq_in[3 * gq + 0], 0.f), 1.f);
        float xq1 = fminf(fmaxf(xq_in[3 * gq + 1], 0.f), 1.f);
        float xq2 = fminf(fmaxf(xq_in[3 * gq + 2], 0.f), 1.f);

        float r3 = ra.w * 0.125f;
        float denom = fmaxf(r3, 1e-5f);
        float s = (r3 > 1e-5f) ? (0.125f / denom) : 0.f;

        dec[0] = ra.x * s; dec[1] = ra.y * s; dec[2] = ra.z * s;
        un0 = rb.x * s; un1 = rb.y * s; un2 = rb.z * s;
        dec[3] = un0; dec[4] = un1; dec[5] = un2;

        const float PI = 3.14159265358979323846f;
        float s1, c1;
        __sincosf(PI * xq0, &s1, &c1);
        float s2 = 2.f * s1 * c1, c2 = 1.f - 2.f * s1 * s1;
        float s4 = 2.f * s2 * c2, c4 = 1.f - 2.f * s2 * s2;
        dec[6] = s1; dec[9] = c1; dec[12] = s2; dec[15] = c2; dec[18] = s4; dec[21] = c4;
        __sincosf(PI * xq1, &s1, &c1);
        s2 = 2.f * s1 * c1; c2 = 1.f - 2.f * s1 * s1;
        s4 = 2.f * s2 * c2; c4 = 1.f - 2.f * s2 * s2;
        dec[7] = s1; dec[10] = c1; dec[13] = s2; dec[16] = c2; dec[19] = s4; dec[22] = c4;
        __sincosf(PI * xq2, &s1, &c1);
        s2 = 2.f * s1 * c1; c2 = 1.f - 2.f * s1 * s1;
        s4 = 2.f * s2 * c2; c4 = 1.f - 2.f * s2 * s2;
        dec[8] = s1; dec[11] = c1; dec[14] = s2; dec[17] = c2; dec[20] = s4; dec[23] = c4;
    }
#pragma unroll
    for (int i = 0; i < 24; i++) sm[OFF_A0 + i * 128 + tid] = dec[i];
    __syncthreads();

    int tq = tid & 15;   // query-tile index (8 queries each)
    int tj = tid >> 4;   // neuron-tile index (8 neurons each)

    // ---- phase 1: C1[q][j] = A0 @ W1 + b1 ; acc lanes = query pairs
    unsigned long long acc[4][8];
#pragma unroll
    for (int jj = 0; jj < 8; jj++) {
        float b = sm[OFF_B1 + tj * 8 + jj];
        unsigned long long bd = pk2(b, b);
#pragma unroll
        for (int qp = 0; qp < 4; qp++) acc[qp][jj] = bd;
    }
#pragma unroll 8
    for (int k = 0; k < 24; k++) {
        const ulonglong2* ap = reinterpret_cast<const ulonglong2*>(&sm[OFF_A0 + k * 128 + tq * 8]);
        ulonglong2 aA = ap[0], aB = ap[1];
        unsigned long long av[4] = {aA.x, aA.y, aB.x, aB.y};
        const float4* wp = reinterpret_cast<const float4*>(&sm[OFF_W1 + k * 64 + tj * 8]);
        float4 w0 = wp[0], w1 = wp[1];
        float wv[8] = {w0.x, w0.y, w0.z, w0.w, w1.x, w1.y, w1.z, w1.w};
#pragma unroll
        for (int jj = 0; jj < 8; jj++) {
            unsigned long long wd = pk2(wv[jj], wv[jj]);
#pragma unroll
            for (int qp = 0; qp < 4; qp++) acc[qp][jj] = ffma2(av[qp], wd, acc[qp][jj]);
        }
    }
    // gelu + store A1[j][q] (q-pair packed)
#pragma unroll
    for (int jj = 0; jj < 8; jj++) {
#pragma unroll
        for (int qp = 0; qp < 4; qp++) {
            float lo, hi;
            upk2(acc[qp][jj], lo, hi);
            unsigned long long g = pk2(gelu_f(lo), gelu_f(hi));
            *reinterpret_cast<unsigned long long*>(
                &sm[OFF_A1 + (tj * 8 + jj) * 128 + tq * 8 + qp * 2]) = g;
        }
    }
    __syncthreads();

    // ---- phase 2: C2[q][j] = gelu(C1) @ W2 + b2
#pragma unroll
    for (int jj = 0; jj < 8; jj++) {
        float b = sm[OFF_B2 + tj * 8 + jj];
        unsigned long long bd = pk2(b, b);
#pragma unroll
        for (int qp = 0; qp < 4; qp++) acc[qp][jj] = bd;
    }
#pragma unroll 8
    for (int k = 0; k < 64; k++) {
        const ulonglong2* ap = reinterpret_cast<const ulonglong2*>(&sm[OFF_A1 + k * 128 + tq * 8]);
        ulonglong2 aA = ap[0], aB = ap[1];
        unsigned long long av[4] = {aA.x, aA.y, aB.x, aB.y};
        const float4* wp = reinterpret_cast<const float4*>(&sm[OFF_W2 + k * 64 + tj * 8]);
        float4 w0 = wp[0], w1 = wp[1];
        float wv[8] = {w0.x, w0.y, w0.z, w0.w, w1.x, w1.y, w1.z, w1.w};
#pragma unroll
        for (int jj = 0; jj < 8; jj++) {
            unsigned long long wd = pk2(wv[jj], wv[jj]);
#pragma unroll
            for (int qp = 0; qp < 4; qp++) acc[qp][jj] = ffma2(av[qp], wd, acc[qp][jj]);
        }
    }

    // ---- phase 3: r[q][c] = gelu(C2) @ W3 ; partials over this thread's 8 j's
    float r[8][3];
#pragma unroll
    for (int qq = 0; qq < 8; qq++) { r[qq][0] = 0.f; r[qq][1] = 0.f; r[qq][2] = 0.f; }
#pragma unroll
    for (int jj = 0; jj < 8; jj++) {
        int j = tj * 8 + jj;
        float w30 = sm[OFF_W3 + j * 4 + 0];
        float w31 = sm[OFF_W3 + j * 4 + 1];
        float w32 = sm[OFF_W3 + j * 4 + 2];
#pragma unroll
        for (int qp = 0; qp < 4; qp++) {
            float lo, hi;
            upk2(acc[qp][jj], lo, hi);
            float g0 = gelu_f(lo), g1 = gelu_f(hi);
            r[qp * 2 + 0][0] += g0 * w30; r[qp * 2 + 0][1] += g0 * w31; r[qp * 2 + 0][2] += g0 * w32;
            r[qp * 2 + 1][0] += g1 * w30; r[qp * 2 + 1][1] += g1 * w31; r[qp * 2 + 1][2] += g1 * w32;
        }
    }
    // write partials to A0 region (free after phase 1): [tj][q][c]
#pragma unroll
    for (int qq = 0; qq < 8; qq++) {
        int q = tq * 8 + qq;
        sm[OFF_A0 + tj * 384 + q * 3 + 0] = r[qq][0];
        sm[OFF_A0 + tj * 384 + q * 3 + 1] = r[qq][1];
        sm[OFF_A0 + tj * 384 + q * 3 + 2] = r[qq][2];
    }
    __syncthreads();

    // reduce 8 partials per query; thread tid owns query tid
    if (gq < M) {
        float r0 = sm[OFF_B3 + 0], r1 = sm[OFF_B3 + 1], r2 = sm[OFF_B3 + 2];
#pragma unroll
        for (int t = 0; t < 8; t++) {
            r0 += sm[OFF_A0 + t * 384 + tid * 3 + 0];
            r1 += sm[OFF_A0 + t * 384 + tid * 3 + 1];
            r2 += sm[OFF_A0 + t * 384 + tid * 3 + 2];
        }
        out[3 * gq + 0] = fminf(fmaxf(un0 + r0, 0.001f), 0.999f);
        out[3 * gq + 1] = fminf(fmaxf(un1 + r1, 0.001f), 0.999f);
        out[3 * gq + 2] = fminf(fmaxf(un2 + r2, 0.001f), 0.999f);
    }
}

// ---------------------------------------------------------------------------
extern "C" void kernel_launch(void* const* d_in, const int* in_sizes, int n_in,
                              void* d_out, int out_size) {
    const float* xq  = (const float*)d_in[0];
    const float* xsr = (const float*)d_in[1];
    const float* xsc = (const float*)d_in[2];
    const float* Wf  = (const float*)d_in[3];
    const float* bf  = (const float*)d_in[4];
    const float* W1  = (const float*)d_in[5];
    const float* b1  = (const float*)d_in[6];
    const float* W2  = (const float*)d_in[7];
    const float* b2  = (const float*)d_in[8];
    const float* W3  = (const float*)d_in[9];
    const float* b3  = (const float*)d_in[10];
    int M = in_sizes[0] / 3;
    int N = in_sizes[1] / 3;

    static int smem_set = 0;
    if (!smem_set) {
        cudaFuncSetAttribute(mlp_kernel,
                             cudaFuncAttributeMaxDynamicSharedMemorySize, SMEM_BYTES);
        smem_set = 1;
    }

    zero_grid_kernel<<<2048, 256>>>();
    p2g_kernel<<<(N + 255) / 256, 256>>>(xsr, xsc, Wf, bf, N);
    long long nthreads = (long long)M * 8;
    gather_kernel<<<(unsigned)((nthreads + 255) / 256), 256>>>(xq, M);
    mlp_kernel<<<(M + QB - 1) / QB, QB, SMEM_BYTES>>>(xq, W1, b1, W2, b2, W3, b3,
                                                      (float*)d_out, M);
}

// round 13
// speedup vs baseline: 1.8718x; 1.0275x over previous
#include <cuda_runtime.h>
#include <math.h>

#define GRID_R 128
#define NCELL (GRID_R*GRID_R*GRID_R)
#define MAXQ 1100000
#define QB 128

// 128^3 cells x 8 channels (7 used + 1 pad) = 64 MiB static scratch
__device__ float g_grid[NCELL * 8];
// per-query reduced gather result (8 floats: 7 channels + pad), 32B/query
__device__ float g_raw[MAXQ * 8];

// fast gelu: tanh via overflow-safe exp identity (MUFU EX2 + MUFU div)
__device__ __forceinline__ float gelu_f(float x) {
    const float C  = 0.7978845608028654f;
    const float C3 = 0.7978845608028654f * 0.044715f;
    float y = x * (C + C3 * x * x);
    float a = fabsf(y);
    float e = __expf(-2.f * a);
    float t = __fdividef(1.f - e, 1.f + e);
    t = copysignf(t, y);
    return 0.5f * x * (1.f + t);
}

// ---------------- packed f32x2 helpers (sm_103a FFMA2 path) ----------------
__device__ __forceinline__ unsigned long long pk2(float lo, float hi) {
    unsigned long long r;
    asm("mov.b64 %0, {%1, %2};" : "=l"(r) : "f"(lo), "f"(hi));
    return r;
}
__device__ __forceinline__ void upk2(unsigned long long v, float& lo, float& hi) {
    asm("mov.b64 {%0, %1}, %2;" : "=f"(lo), "=f"(hi) : "l"(v));
}
__device__ __forceinline__ unsigned long long ffma2(unsigned long long a,
                                                    unsigned long long b,
                                                    unsigned long long c) {
    unsigned long long d;
    asm("fma.rn.f32x2 %0, %1, %2, %3;" : "=l"(d) : "l"(a), "l"(b), "l"(c));
    return d;
}

// ---------------------------------------------------------------------------
// Kernel 1: zero the grid (grid-stride)
// ---------------------------------------------------------------------------
__global__ void zero_grid_kernel() {
    float4* g = reinterpret_cast<float4*>(g_grid);
    unsigned stride = gridDim.x * blockDim.x;
    for (unsigned i = blockIdx.x * blockDim.x + threadIdx.x;
         i < (unsigned)(NCELL * 2); i += stride) {
        g[i] = make_float4(0.f, 0.f, 0.f, 0.f);
    }
}

// ---------------------------------------------------------------------------
// Kernel 2: particle-to-grid trilinear scatter (vector reductions)
// ---------------------------------------------------------------------------
__device__ __forceinline__ void red_add_v4(float* addr, float a, float b, float c, float d) {
    asm volatile("red.global.add.v4.f32 [%0], {%1,%2,%3,%4};"
                 :: "l"(addr), "f"(a), "f"(b), "f"(c), "f"(d) : "memory");
}

__global__ __launch_bounds__(256) void p2g_kernel(
    const float* __restrict__ src_ref,
    const float* __restrict__ src_curr,
    const float* __restrict__ Wf,
    const float* __restrict__ bf,
    int N) {
    int i = blockIdx.x * blockDim.x + threadIdx.x;
    if (i >= N) return;

    float xs0 = fminf(fmaxf(src_ref[3 * i + 0], 0.f), 1.f);
    float xs1 = fminf(fmaxf(src_ref[3 * i + 1], 0.f), 1.f);
    float xs2 = fminf(fmaxf(src_ref[3 * i + 2], 0.f), 1.f);
    float u0 = src_curr[3 * i + 0] - xs0;
    float u1 = src_curr[3 * i + 1] - xs1;
    float u2 = src_curr[3 * i + 2] - xs2;

    float f0 = gelu_f(bf[0] + u0 * Wf[0] + u1 * Wf[3] + u2 * Wf[6]);
    float f1 = gelu_f(bf[1] + u0 * Wf[1] + u1 * Wf[4] + u2 * Wf[7]);
    float f2 = gelu_f(bf[2] + u0 * Wf[2] + u1 * Wf[5] + u2 * Wf[8]);

    float cx = fminf(xs0 * 127.f, 126.999f);
    float cy = fminf(xs1 * 127.f, 126.999f);
    float cz = fminf(xs2 * 127.f, 126.999f);
    int bx = (int)cx, by = (int)cy, bz = (int)cz;
    float dx = cx - (float)bx, dy = cy - (float)by, dz = cz - (float)bz;

#pragma unroll
    for (int ox = 0; ox < 2; ox++) {
        float wx = ox ? dx : 1.f - dx;
#pragma unroll
        for (int oy = 0; oy < 2; oy++) {
            float wxy = wx * (oy ? dy : 1.f - dy);
#pragma unroll
            for (int oz = 0; oz < 2; oz++) {
                float w = wxy * (oz ? dz : 1.f - dz);
                int cell = ((((bx + ox) << 7) + (by + oy)) << 7) + (bz + oz);
                float* p = g_grid + cell * 8;
                red_add_v4(p,     f0 * w, f1 * w, f2 * w, w);
                red_add_v4(p + 4, u0 * w, u1 * w, u2 * w, 0.f);
            }
        }
    }
}

// ---------------------------------------------------------------------------
// threefry2x32 with key = (0, 42), matching jax.random.key(42)
// ---------------------------------------------------------------------------
__device__ __forceinline__ void tf_round(unsigned& v0, unsigned& v1, int r) {
    v0 += v1;
    v1 = __funnelshift_l(v1, v1, r);
    v1 ^= v0;
}

__device__ __forceinline__ uint2 threefry_0_42(unsigned x0, unsigned x1) {
    const unsigned k0 = 0u, k1 = 42u;
    const unsigned k2 = 0u ^ 42u ^ 0x1BD11BDAu;
    unsigned v0 = x0 + k0, v1 = x1 + k1;
    tf_round(v0, v1, 13); tf_round(v0, v1, 15); tf_round(v0, v1, 26); tf_round(v0, v1, 6);
    v0 += k1; v1 += k2 + 1u;
    tf_round(v0, v1, 17); tf_round(v0, v1, 29); tf_round(v0, v1, 16); tf_round(v0, v1, 24);
    v0 += k2; v1 += k0 + 2u;
    tf_round(v0, v1, 13); tf_round(v0, v1, 15); tf_round(v0, v1, 26); tf_round(v0, v1, 6);
    v0 += k0; v1 += k1 + 3u;
    tf_round(v0, v1, 17); tf_round(v0, v1, 29); tf_round(v0, v1, 16); tf_round(v0, v1, 24);
    v0 += k1; v1 += k2 + 4u;
    tf_round(v0, v1, 13); tf_round(v0, v1, 15); tf_round(v0, v1, 26); tf_round(v0, v1, 6);
    v0 += k2; v1 += k0 + 5u;
    return make_uint2(v0, v1);
}

// jax_threefry_partitionable=True: bits[j] = w0 ^ w1 of threefry(key, (0, j))
__device__ __forceinline__ unsigned tf_bits_partitionable(unsigned j) {
    uint2 r = threefry_0_42(0u, j);
    return r.x ^ r.y;
}

__device__ __forceinline__ float bits_to_normal(unsigned b) {
    float f = __uint_as_float((b >> 9) | 0x3f800000u) - 1.0f;
    float u = f * 2.0f - 0.99999994f;
    u = fmaxf(u, -0.99999994f);
    return 1.4142135623730951f * erfinvf(u);
}

// ---------------------------------------------------------------------------
// Kernel 3: gather — 8 threads per query (one per MC path), shfl-reduce
// ---------------------------------------------------------------------------
__global__ __launch_bounds__(256) void gather_kernel(
    const float* __restrict__ xq_in, int M) {

    int tid = blockIdx.x * blockDim.x + threadIdx.x;
    int m  = tid >> 3;
    int kk = tid & 7;
    if (m >= M) return;

    float q0 = fminf(fmaxf(xq_in[3 * m + 0], 0.f), 1.f) * 127.f;
    float q1 = fminf(fmaxf(xq_in[3 * m + 1], 0.f), 1.f) * 127.f;
    float q2 = fminf(fmaxf(xq_in[3 * m + 2], 0.f), 1.f) * 127.f;

    unsigned jb = ((unsigned)kk * (unsigned)M + (unsigned)m) * 3u;
    float px = q0 + 0.8f * bits_to_normal(tf_bits_partitionable(jb + 0u));
    float py = q1 + 0.8f * bits_to_normal(tf_bits_partitionable(jb + 1u));
    float pz = q2 + 0.8f * bits_to_normal(tf_bits_partitionable(jb + 2u));

    float fx = floorf(px), fy = floorf(py), fz = floorf(pz);
    float dx = px - fx, dy = py - fy, dz = pz - fz;
    int lx = (int)fx, ly = (int)fy, lz = (int)fz;
    int x0i = min(max(lx, 0), 127), x1i = min(max(lx + 1, 0), 127);
    int y0i = min(max(ly, 0), 127), y1i = min(max(ly + 1, 0), 127);
    int z0i = min(max(lz, 0), 127), z1i = min(max(lz + 1, 0), 127);

    unsigned long long acc01 = 0ull, acc23 = 0ull, acc45 = 0ull, acc67 = 0ull;

#pragma unroll
    for (int cx = 0; cx < 2; cx++) {
        int ix = cx ? x1i : x0i;
        float wx = cx ? dx : 1.f - dx;
#pragma unroll
        for (int cy = 0; cy < 2; cy++) {
            int iy = cy ? y1i : y0i;
            float wxy = wx * (cy ? dy : 1.f - dy);
#pragma unroll
            for (int cz = 0; cz < 2; cz++) {
                int iz = cz ? z1i : z0i;
                float w = wxy * (cz ? dz : 1.f - dz);
                int cell = (((ix << 7) + iy) << 7) + iz;
                const ulonglong2* g =
                    reinterpret_cast<const ulonglong2*>(g_grid + cell * 8);
                ulonglong2 va = g[0];
                ulonglong2 vb = g[1];
                unsigned long long ws = pk2(w, w);
                acc01 = ffma2(va.x, ws, acc01);
                acc23 = ffma2(va.y, ws, acc23);
                acc45 = ffma2(vb.x, ws, acc45);
                acc67 = ffma2(vb.y, ws, acc67);
            }
        }
    }

#pragma unroll
    for (int d = 4; d >= 1; d >>= 1) {
        float lo, hi, slo, shi;
        upk2(acc01, lo, hi);
        slo = __shfl_xor_sync(0xffffffffu, lo, d);
        shi = __shfl_xor_sync(0xffffffffu, hi, d);
        acc01 = pk2(lo + slo, hi + shi);
        upk2(acc23, lo, hi);
        slo = __shfl_xor_sync(0xffffffffu, lo, d);
        shi = __shfl_xor_sync(0xffffffffu, hi, d);
        acc23 = pk2(lo + slo, hi + shi);
        upk2(acc45, lo, hi);
        slo = __shfl_xor_sync(0xffffffffu, lo, d);
        shi = __shfl_xor_sync(0xffffffffu, hi, d);
        acc45 = pk2(lo + slo, hi + shi);
        upk2(acc67, lo, hi);
        slo = __shfl_xor_sync(0xffffffffu, lo, d);
        shi = __shfl_xor_sync(0xffffffffu, hi, d);
        acc67 = pk2(lo + slo, hi + shi);
    }

    if (kk == 0) {
        ulonglong2* dst = reinterpret_cast<ulonglong2*>(g_raw + (size_t)m * 8);
        ulonglong2 v0; v0.x = acc01; v0.y = acc23;
        ulonglong2 v1; v1.x = acc45; v1.y = acc67;
        dst[0] = v0;
        dst[1] = v1;
    }
}

// ---------------------------------------------------------------------------
// Kernel 4: block-GEMM MLP — 128 queries/block, 8q x 8n register tiles
// smem layout (float idx): W2/A0/partials share one region -> 55.6 KB, 4 CTAs/SM
// ---------------------------------------------------------------------------
#define OFF_W1 0        // 24*64 = 1536
#define OFF_W3 1536     // 64*4  = 256
#define OFF_B1 1792     // 64
#define OFF_B2 1856     // 64
#define OFF_B3 1920     // 32 (pad)
#define OFF_A1 1952     // 64*128 = 8192
#define OFF_X  10144    // 4096: phase0-1 A0 (24*128=3072), phase2 W2 (4096), phase3 partials (3072)
#define OFF_A0 OFF_X
#define OFF_W2 OFF_X
#define SMEM_FLOATS 14240
#define SMEM_BYTES (SMEM_FLOATS * 4)

__global__ __launch_bounds__(QB, 4) void mlp_kernel(
    const float* __restrict__ xq_in,
    const float* __restrict__ W1, const float* __restrict__ b1,
    const float* __restrict__ W2, const float* __restrict__ b2,
    const float* __restrict__ W3, const float* __restrict__ b3,
    float* __restrict__ out, int M) {

    extern __shared__ float sm[];
    int tid = threadIdx.x;

    // stage small weights (W2 staged later, after A0 is dead)
    for (int t = tid; t < 1536; t += QB) sm[OFF_W1 + t] = W1[t];
    for (int t = tid; t < 192; t += QB) { int j = t / 3, c = t % 3; sm[OFF_W3 + j * 4 + c] = W3[t]; }
    for (int t = tid; t < 64; t += QB) { sm[OFF_B1 + t] = b1[t]; sm[OFF_B2 + t] = b2[t]; }
    if (tid < 3) sm[OFF_B3 + tid] = b3[tid];

    // ---- phase 0: per-thread dec[24] for query gq, store transposed A0[i][q]
    int gq = blockIdx.x * QB + tid;
    float un0 = 0.f, un1 = 0.f, un2 = 0.f;
    float dec[24];
#pragma unroll
    for (int i = 0; i < 24; i++) dec[i] = 0.f;

    if (gq < M) {
        const float4* raw = reinterpret_cast<const float4*>(g_raw + (size_t)gq * 8);
        float4 ra = raw[0];
        float4 rb = raw[1];
        float xq0 = fminf(fmaxf(xq_in[3 * gq + 0], 0.f), 1.f);
        float xq1 = fminf(fmaxf(xq_in[3 * gq + 1], 0.f), 1.f);
        float xq2 = fminf(fmaxf(xq_in[3 * gq + 2], 0.f), 1.f);

        float r3 = ra.w * 0.125f;
        float denom = fmaxf(r3, 1e-5f);
        float s = (r3 > 1e-5f) ? (0.125f / denom) : 0.f;

        dec[0] = ra.x * s; dec[1] = ra.y * s; dec[2] = ra.z * s;
        un0 = rb.x * s; un1 = rb.y * s; un2 = rb.z * s;
        dec[3] = un0; dec[4] = un1; dec[5] = un2;

        const float PI = 3.14159265358979323846f;
        float s1, c1;
        __sincosf(PI * xq0, &s1, &c1);
        float s2 = 2.f * s1 * c1, c2 = 1.f - 2.f * s1 * s1;
        float s4 = 2.f * s2 * c2, c4 = 1.f - 2.f * s2 * s2;
        dec[6] = s1; dec[9] = c1; dec[12] = s2; dec[15] = c2; dec[18] = s4; dec[21] = c4;
        __sincosf(PI * xq1, &s1, &c1);
        s2 = 2.f * s1 * c1; c2 = 1.f - 2.f * s1 * s1;
        s4 = 2.f * s2 * c2; c4 = 1.f - 2.f * s2 * s2;
        dec[7] = s1; dec[10] = c1; dec[13] = s2; dec[16] = c2; dec[19] = s4; dec[22] = c4;
        __sincosf(PI * xq2, &s1, &c1);
        s2 = 2.f * s1 * c1; c2 = 1.f - 2.f * s1 * s1;
        s4 = 2.f * s2 * c2; c4 = 1.f - 2.f * s2 * s2;
        dec[8] = s1; dec[11] = c1; dec[14] = s2; dec[17] = c2; dec[20] = s4; dec[23] = c4;
    }
#pragma unroll
    for (int i = 0; i < 24; i++) sm[OFF_A0 + i * 128 + tid] = dec[i];
    __syncthreads();

    int tq = tid & 15;   // query-tile index (8 queries each)
    int tj = tid >> 4;   // neuron-tile index (8 neurons each)

    // ---- phase 1: C1[q][j] = A0 @ W1 + b1 ; acc lanes = query pairs
    unsigned long long acc[4][8];
#pragma unroll
    for (int jj = 0; jj < 8; jj++) {
        float b = sm[OFF_B1 + tj * 8 + jj];
        unsigned long long bd = pk2(b, b);
#pragma unroll
        for (int qp = 0; qp < 4; qp++) acc[qp][jj] = bd;
    }
#pragma unroll 8
    for (int k = 0; k < 24; k++) {
        const ulonglong2* ap = reinterpret_cast<const ulonglong2*>(&sm[OFF_A0 + k * 128 + tq * 8]);
        ulonglong2 aA = ap[0], aB = ap[1];
        unsigned long long av[4] = {aA.x, aA.y, aB.x, aB.y};
        const float4* wp = reinterpret_cast<const float4*>(&sm[OFF_W1 + k * 64 + tj * 8]);
        float4 w0 = wp[0], w1 = wp[1];
        float wv[8] = {w0.x, w0.y, w0.z, w0.w, w1.x, w1.y, w1.z, w1.w};
#pragma unroll
        for (int jj = 0; jj < 8; jj++) {
            unsigned long long wd = pk2(wv[jj], wv[jj]);
#pragma unroll
            for (int qp = 0; qp < 4; qp++) acc[qp][jj] = ffma2(av[qp], wd, acc[qp][jj]);
        }
    }
    // gelu + store A1[j][q] (q-pair packed)
#pragma unroll
    for (int jj = 0; jj < 8; jj++) {
#pragma unroll
        for (int qp = 0; qp < 4; qp++) {
            float lo, hi;
            upk2(acc[qp][jj], lo, hi);
            unsigned long long g = pk2(gelu_f(lo), gelu_f(hi));
            *reinterpret_cast<unsigned long long*>(
                &sm[OFF_A1 + (tj * 8 + jj) * 128 + tq * 8 + qp * 2]) = g;
        }
    }
    __syncthreads();   // A0 dead beyond this point

    // stage W2 into the shared X region (L2-hot, 16 KB)
    {
        const float4* src = reinterpret_cast<const float4*>(W2);
        float4* dst = reinterpret_cast<float4*>(&sm[OFF_W2]);
        for (int t = tid; t < 1024; t += QB) dst[t] = src[t];
    }
    __syncthreads();

    // ---- phase 2: C2[q][j] = gelu(C1) @ W2 + b2
#pragma unroll
    for (int jj = 0; jj < 8; jj++) {
        float b = sm[OFF_B2 + tj * 8 + jj];
        unsigned long long bd = pk2(b, b);
#pragma unroll
        for (int qp = 0; qp < 4; qp++) acc[qp][jj] = bd;
    }
#pragma unroll 8
    for (int k = 0; k < 64; k++) {
        const ulonglong2* ap = reinterpret_cast<const ulonglong2*>(&sm[OFF_A1 + k * 128 + tq * 8]);
        ulonglong2 aA = ap[0], aB = ap[1];
        unsigned long long av[4] = {aA.x, aA.y, aB.x, aB.y};
        const float4* wp = reinterpret_cast<const float4*>(&sm[OFF_W2 + k * 64 + tj * 8]);
        float4 w0 = wp[0], w1 = wp[1];
        float wv[8] = {w0.x, w0.y, w0.z, w0.w, w1.x, w1.y, w1.z, w1.w};
#pragma unroll
        for (int jj = 0; jj < 8; jj++) {
            unsigned long long wd = pk2(wv[jj], wv[jj]);
#pragma unroll
            for (int qp = 0; qp < 4; qp++) acc[qp][jj] = ffma2(av[qp], wd, acc[qp][jj]);
        }
    }
    __syncthreads();   // W2 dead beyond this point (partials reuse the region)

    // ---- phase 3: r[q][c] = gelu(C2) @ W3 ; partials over this thread's 8 j's
    float r[8][3];
#pragma unroll
    for (int qq = 0; qq < 8; qq++) { r[qq][0] = 0.f; r[qq][1] = 0.f; r[qq][2] = 0.f; }
#pragma unroll
    for (int jj = 0; jj < 8; jj++) {
        int j = tj * 8 + jj;
        float w30 = sm[OFF_W3 + j * 4 + 0];
        float w31 = sm[OFF_W3 + j * 4 + 1];
        float w32 = sm[OFF_W3 + j * 4 + 2];
#pragma unroll
        for (int qp = 0; qp < 4; qp++) {
            float lo, hi;
            upk2(acc[qp][jj], lo, hi);
            float g0 = gelu_f(lo), g1 = gelu_f(hi);
            r[qp * 2 + 0][0] += g0 * w30; r[qp * 2 + 0][1] += g0 * w31; r[qp * 2 + 0][2] += g0 * w32;
            r[qp * 2 + 1][0] += g1 * w30; r[qp * 2 + 1][1] += g1 * w31; r[qp * 2 + 1][2] += g1 * w32;
        }
    }
    // write partials to X region: [tj][q][c]
#pragma unroll
    for (int qq = 0; qq < 8; qq++) {
        int q = tq * 8 + qq;
        sm[OFF_X + tj * 384 + q * 3 + 0] = r[qq][0];
        sm[OFF_X + tj * 384 + q * 3 + 1] = r[qq][1];
        sm[OFF_X + tj * 384 + q * 3 + 2] = r[qq][2];
    }
    __syncthreads();

    // reduce 8 partials per query; thread tid owns query tid
    if (gq < M) {
        float r0 = sm[OFF_B3 + 0], r1 = sm[OFF_B3 + 1], r2 = sm[OFF_B3 + 2];
#pragma unroll
        for (int t = 0; t < 8; t++) {
            r0 += sm[OFF_X + t * 384 + tid * 3 + 0];
            r1 += sm[OFF_X + t * 384 + tid * 3 + 1];
            r2 += sm[OFF_X + t * 384 + tid * 3 + 2];
        }
        out[3 * gq + 0] = fminf(fmaxf(un0 + r0, 0.001f), 0.999f);
        out[3 * gq + 1] = fminf(fmaxf(un1 + r1, 0.001f), 0.999f);
        out[3 * gq + 2] = fminf(fmaxf(un2 + r2, 0.001f), 0.999f);
    }
}

// ---------------------------------------------------------------------------
extern "C" void kernel_launch(void* const* d_in, const int* in_sizes, int n_in,
                              void* d_out, int out_size) {
    const float* xq  = (const float*)d_in[0];
    const float* xsr = (const float*)d_in[1];
    const float* xsc = (const float*)d_in[2];
    const float* Wf  = (const float*)d_in[3];
    const float* bf  = (const float*)d_in[4];
    const float* W1  = (const float*)d_in[5];
    const float* b1  = (const float*)d_in[6];
    const float* W2  = (const float*)d_in[7];
    const float* b2  = (const float*)d_in[8];
    const float* W3  = (const float*)d_in[9];
    const float* b3  = (const float*)d_in[10];
    int M = in_sizes[0] / 3;
    int N = in_sizes[1] / 3;

    static int smem_set = 0;
    if (!smem_set) {
        cudaFuncSetAttribute(mlp_kernel,
                             cudaFuncAttributeMaxDynamicSharedMemorySize, SMEM_BYTES);
        smem_set = 1;
    }

    zero_grid_kernel<<<2048, 256>>>();
    p2g_kernel<<<(N + 255) / 256, 256>>>(xsr, xsc, Wf, bf, N);
    long long nthreads = (long long)M * 8;
    gather_kernel<<<(unsigned)((nthreads + 255) / 256), 256>>>(xq, M);
    mlp_kernel<<<(M + QB - 1) / QB, QB, SMEM_BYTES>>>(xq, W1, b1, W2, b2, W3, b3,
                                                      (float*)d_out, M);
}